// round 2
// baseline (speedup 1.0000x reference)
#include <cuda_runtime.h>
#include <cooperative_groups.h>
#include <math_constants.h>

namespace cg = cooperative_groups;

#define CS   8
#define TPB  256

// ---- shared memory layout (float offsets) ----
static constexpr int PADW     = 132;                     // padded row stride for 128-wide matrices
static constexpr int OFF_WRT  = 0;                       // 128*132: Ws/Wt staging, then Wr (row-major, padded)
static constexpr int OFF_WHS  = OFF_WRT + 128 * PADW;    // 32*128  : my 32 q-rows of W_hs
static constexpr int OFF_WG   = OFF_WHS + 32 * 128;      // 32*256  : q/p staging, then Wg slice
static constexpr int OFF_WIH  = OFF_WG + 32 * 256;       // 64*256  : Wih slice
static constexpr int OFF_WHH  = OFF_WIH + 64 * 256;      // 64*128  : Whh slice
static constexpr int OFF_WE   = OFF_WHH + 64 * 128;      // 128
static constexpr int OFF_WRB  = OFF_WE + 128;            // 128
static constexpr int OFF_WGB  = OFF_WRB + 128;           // 32
static constexpr int OFF_BIHH = OFF_WGB + 32;            // 64 : bih+bhh slice
static constexpr int OFF_U    = OFF_BIHH + 64;           // 128
static constexpr int OFF_H    = OFF_U + 128;             // 128
static constexpr int OFF_C    = OFF_H + 128;             // 128
static constexpr int OFF_X    = OFF_C + 128;             // 256 : [alpha, p_t]
static constexpr int OFF_XP   = OFF_X + 256;             // 256 : gathered gated x
static constexpr int OFF_SC   = OFF_XP + 256;            // 32  : local scores
static constexpr int OFF_PQ   = OFF_SC + 32;             // 32  : exp(s - m_local)
static constexpr int OFF_COEF = OFF_PQ + 32;             // 8   : per-rank softmax coefficients
static constexpr int OFF_STAT = OFF_COEF + 8;            // 4   : [0]=1/L, [1]=m_local, [2]=l_local
static constexpr int OFF_ACCE = OFF_STAT + 4;            // 128 : sum_q e^{s-m} W_hs[q][h]  (exported)
static constexpr int OFF_XGE  = OFF_ACCE + 128;          // 32  : gated-x slice (exported)
static constexpr int OFF_GTE  = OFF_XGE + 32;            // 64  : gate pre-activations slice (exported)
static constexpr int SMEM_FLOATS = OFF_GTE + 64;         // 55308 floats = 221232 bytes

// wt_pre scratch: [B=16][P=128][H=128]
__device__ float g_wtp[16 * 128 * 128];

__device__ __forceinline__ float fast_tanh(float x) {
    float y; asm("tanh.approx.f32 %0, %1;" : "=f"(y) : "f"(x)); return y;
}
__device__ __forceinline__ float sigm(float x) {
    return __fdividef(1.f, 1.f + __expf(-x));
}
__device__ __forceinline__ float tanh_ex(float x) {   // accurate-enough tanh for the LSTM cell
    float e = __expf(2.f * x);
    return 1.f - __fdividef(2.f, e + 1.f);
}
__device__ __forceinline__ float warp_sum(float v) {
    #pragma unroll
    for (int o = 16; o; o >>= 1) v += __shfl_xor_sync(0xffffffffu, v, o);
    return v;
}
__device__ __forceinline__ float warp_max(float v) {
    #pragma unroll
    for (int o = 16; o; o >>= 1) v = fmaxf(v, __shfl_xor_sync(0xffffffffu, v, o));
    return v;
}

__global__ void __launch_bounds__(TPB, 1) __cluster_dims__(CS, 1, 1)
mlstm_kernel(const float* __restrict__ p_in,  const float* __restrict__ q_in,
             const float* __restrict__ Ws_w,  const float* __restrict__ Ws_b,
             const float* __restrict__ Wt_w,  const float* __restrict__ Wt_b,
             const float* __restrict__ Wr_w,  const float* __restrict__ Wr_b,
             const float* __restrict__ We_w,
             const float* __restrict__ Wg_w,  const float* __restrict__ Wg_b,
             const float* __restrict__ Wih,   const float* __restrict__ Whh,
             const float* __restrict__ bih,   const float* __restrict__ bhh,
             float* __restrict__ out)
{
    extern __shared__ float s[];
    cg::cluster_group cl = cg::this_cluster();
    const int rank = (int)cl.block_rank();
    const int b    = (int)(blockIdx.x >> 3);
    const int tid  = (int)threadIdx.x;
    const int lane = tid & 31;
    const int warp = tid >> 5;

    // ============================ PROLOGUE ============================
    // --- S_A: stage Ws (row-major, padded) + my 32 q rows; compute W_hs slice ---
    for (int i4 = tid; i4 < 4096; i4 += TPB) {
        int hh = i4 >> 5, k = i4 & 31;
        *(float4*)&s[OFF_WRT + hh * PADW + k * 4] = ((const float4*)Ws_w)[i4];
    }
    for (int i4 = tid; i4 < 1024; i4 += TPB)
        ((float4*)&s[OFF_WG])[i4] = ((const float4*)(q_in + (size_t)(b * 256 + rank * 32) * 128))[i4];
    __syncthreads();
    {
        int hh = tid & 127, q0 = (tid >> 7) * 16;
        const float4* wrow = (const float4*)&s[OFF_WRT + hh * PADW];
        float acc[16];
        float sb = Ws_b[hh];
        #pragma unroll
        for (int i = 0; i < 16; i++) acc[i] = sb;
        for (int k = 0; k < 32; k++) {
            float4 w = wrow[k];
            #pragma unroll
            for (int i = 0; i < 16; i++) {
                float4 qv = *(const float4*)&s[OFF_WG + (q0 + i) * 128 + k * 4];
                acc[i] += w.x * qv.x + w.y * qv.y + w.z * qv.z + w.w * qv.w;
            }
        }
        #pragma unroll
        for (int i = 0; i < 16; i++) s[OFF_WHS + (q0 + i) * 128 + hh] = acc[i];
    }
    __syncthreads();

    // --- S_B: stage Wt + my 16 p rows; compute wt_pre rows -> gmem scratch ---
    for (int i4 = tid; i4 < 4096; i4 += TPB) {
        int hh = i4 >> 5, k = i4 & 31;
        *(float4*)&s[OFF_WRT + hh * PADW + k * 4] = ((const float4*)Wt_w)[i4];
    }
    for (int i4 = tid; i4 < 512; i4 += TPB)
        ((float4*)&s[OFF_WG + 4096])[i4] = ((const float4*)(p_in + (size_t)(b * 128 + rank * 16) * 128))[i4];
    __syncthreads();
    {
        int hh = tid & 127, t0 = (tid >> 7) * 8;
        const float4* wrow = (const float4*)&s[OFF_WRT + hh * PADW];
        float acc[8];
        float bt = Wt_b[hh];
        #pragma unroll
        for (int i = 0; i < 8; i++) acc[i] = bt;
        for (int k = 0; k < 32; k++) {
            float4 w = wrow[k];
            #pragma unroll
            for (int i = 0; i < 8; i++) {
                float4 pv = *(const float4*)&s[OFF_WG + 4096 + (t0 + i) * 128 + k * 4];
                acc[i] += w.x * pv.x + w.y * pv.y + w.z * pv.z + w.w * pv.w;
            }
        }
        #pragma unroll
        for (int i = 0; i < 8; i++)
            g_wtp[(size_t)(b * 128 + rank * 16 + t0 + i) * 128 + hh] = acc[i];
    }
    __syncthreads();

    // --- S_C: load the real resident weights ---
    for (int i4 = tid; i4 < 4096; i4 += TPB) {     // Wr row-major padded
        int hh = i4 >> 5, k = i4 & 31;
        *(float4*)&s[OFF_WRT + hh * PADW + k * 4] = ((const float4*)Wr_w)[i4];
    }
    for (int i4 = tid; i4 < 2048; i4 += TPB)
        ((float4*)&s[OFF_WG])[i4]  = ((const float4*)(Wg_w + (size_t)rank * 32 * 256))[i4];
    for (int i4 = tid; i4 < 4096; i4 += TPB)
        ((float4*)&s[OFF_WIH])[i4] = ((const float4*)(Wih + (size_t)rank * 64 * 256))[i4];
    for (int i4 = tid; i4 < 2048; i4 += TPB)
        ((float4*)&s[OFF_WHH])[i4] = ((const float4*)(Whh + (size_t)rank * 64 * 128))[i4];
    if (tid < 128) {
        s[OFF_WE  + tid] = We_w[tid];
        s[OFF_WRB + tid] = Wr_b[tid];
        s[OFF_H   + tid] = 0.f;
        s[OFF_C   + tid] = 0.f;
    }
    if (tid < 32) s[OFF_WGB + tid] = Wg_b[rank * 32 + tid];
    if (tid < 64) s[OFF_BIHH + tid] = bih[rank * 64 + tid] + bhh[rank * 64 + tid];
    __threadfence();   // make g_wtp visible cluster-wide
    __syncthreads();
    cl.sync();

    const float4 we4 = *(const float4*)&s[OFF_WE + lane * 4];

    // ============================ MAIN LOOP ============================
    for (int t = 0; t < 128; t++) {
        // ---- A: u = wt_pre[t] + Wr_b + Wr @ h  (full, redundant per CTA) ----
        if (tid < 128) {
            int hh = tid;
            const float4* wr = (const float4*)&s[OFF_WRT + hh * PADW];
            const float4* hv = (const float4*)&s[OFF_H];
            float a0 = 0.f, a1 = 0.f, a2 = 0.f, a3 = 0.f;
            #pragma unroll
            for (int k = 0; k < 32; k++) {
                float4 w = wr[k], x = hv[k];
                a0 += w.x * x.x; a1 += w.y * x.y; a2 += w.z * x.z; a3 += w.w * x.w;
            }
            s[OFF_U + hh] = g_wtp[(size_t)(b * 128 + t) * 128 + hh] + s[OFF_WRB + hh]
                            + ((a0 + a1) + (a2 + a3));
        } else {
            int j = tid - 128;
            s[OFF_X + 128 + j] = p_in[(size_t)(b * 128 + t) * 128 + j];
        }
        __syncthreads();

        // ---- B: scores over my 32 q rows ----
        {
            const float4 u4 = *(const float4*)&s[OFF_U + lane * 4];
            #pragma unroll
            for (int qq = 0; qq < 4; qq++) {
                int ql = warp * 4 + qq;
                float4 w4 = *(const float4*)&s[OFF_WHS + ql * 128 + lane * 4];
                float sc = fast_tanh(w4.x + u4.x) * we4.x
                         + fast_tanh(w4.y + u4.y) * we4.y
                         + fast_tanh(w4.z + u4.z) * we4.z
                         + fast_tanh(w4.w + u4.w) * we4.w;
                sc = warp_sum(sc);
                if (lane == 0) s[OFF_SC + ql] = sc;
            }
        }
        __syncthreads();
        if (tid < 32) {          // local softmax partials
            float sc = s[OFF_SC + tid];
            float m  = warp_max(sc);
            float e  = __expf(sc - m);
            s[OFF_PQ + tid] = e;
            float l = warp_sum(e);
            if (tid == 0) { s[OFF_STAT + 1] = m; s[OFF_STAT + 2] = l; }
        }
        __syncthreads();
        if (tid < 128) {         // acc[h] = sum_q e^{s_q-m} * W_hs[q][h]
            float a = 0.f;
            #pragma unroll
            for (int ql = 0; ql < 32; ql++)
                a += s[OFF_PQ + ql] * s[OFF_WHS + ql * 128 + tid];
            s[OFF_ACCE + tid] = a;
        }
        cl.sync();   // barrier 1: partials exported

        // ---- C: combine softmax across cluster; alpha -> x[0:128] ----
        if (tid < 32) {
            float mi = -CUDART_INF_F, li = 0.f;
            if (lane < 8) {
                const float* st = (const float*)cl.map_shared_rank((void*)&s[OFF_STAT], lane);
                mi = st[1]; li = st[2];
            }
            float M  = warp_max(mi);
            float cf = (lane < 8) ? __expf(mi - M) : 0.f;
            if (lane < 8) s[OFF_COEF + lane] = cf;
            float L = warp_sum(cf * li);
            if (lane == 0) s[OFF_STAT] = 1.f / L;
        }
        __syncthreads();
        if (tid < 128) {
            float a = 0.f;
            #pragma unroll
            for (int i = 0; i < 8; i++) {
                const float* ap = (const float*)cl.map_shared_rank((void*)&s[OFF_ACCE + tid], i);
                a += s[OFF_COEF + i] * ap[0];
            }
            s[OFF_X + tid] = a * s[OFF_STAT];
        }
        __syncthreads();

        // ---- D: gate slice g[32]; export x'_slice = g * x ----
        {
            float4 x0 = *(const float4*)&s[OFF_X + lane * 4];
            float4 x1 = *(const float4*)&s[OFF_X + 128 + lane * 4];
            #pragma unroll
            for (int jj = 0; jj < 4; jj++) {
                int j = warp * 4 + jj;
                const float4* wg = (const float4*)&s[OFF_WG + j * 256];
                float4 w0 = wg[lane], w1 = wg[32 + lane];
                float sum = x0.x * w0.x + x0.y * w0.y + x0.z * w0.z + x0.w * w0.w
                          + x1.x * w1.x + x1.y * w1.y + x1.z * w1.z + x1.w * w1.w;
                sum = warp_sum(sum);
                if (lane == 0) {
                    float g = sigm(sum + s[OFF_WGB + j]);
                    s[OFF_XGE + j] = g * s[OFF_X + rank * 32 + j];
                }
            }
        }
        cl.sync();   // barrier 2: x' slices exported

        // ---- E: gather x'[256]; compute my 64 gate pre-activations; export ----
        {
            int peer = tid >> 5, off = tid & 31;
            const float* xp = (const float*)cl.map_shared_rank((void*)&s[OFF_XGE + off], peer);
            s[OFF_XP + tid] = *xp;
        }
        __syncthreads();
        {
            float4 xa = *(const float4*)&s[OFF_XP + lane * 4];
            float4 xb = *(const float4*)&s[OFF_XP + 128 + lane * 4];
            float4 h4 = *(const float4*)&s[OFF_H + lane * 4];
            #pragma unroll
            for (int jj = 0; jj < 8; jj++) {
                int j = warp * 8 + jj;
                const float4* wi = (const float4*)&s[OFF_WIH + j * 256];
                const float4* wh = (const float4*)&s[OFF_WHH + j * 128];
                float4 wa = wi[lane], wb = wi[32 + lane], w2 = wh[lane];
                float sum = xa.x * wa.x + xa.y * wa.y + xa.z * wa.z + xa.w * wa.w
                          + xb.x * wb.x + xb.y * wb.y + xb.z * wb.z + xb.w * wb.w
                          + h4.x * w2.x + h4.y * w2.y + h4.z * w2.z + h4.w * w2.w;
                sum = warp_sum(sum);
                if (lane == 0) s[OFF_GTE + j] = sum + s[OFF_BIHH + j];
            }
        }
        cl.sync();   // barrier 3: gate slices exported

        // ---- F: gather gates; LSTM pointwise (redundant); update h, c ----
        if (tid < 128) {
            int hh = tid;
            int r0 = hh >> 6, sl = hh & 63;
            float gi = *(const float*)cl.map_shared_rank((void*)&s[OFF_GTE + sl], r0);
            float gf = *(const float*)cl.map_shared_rank((void*)&s[OFF_GTE + sl], 2 + r0);
            float gg = *(const float*)cl.map_shared_rank((void*)&s[OFF_GTE + sl], 4 + r0);
            float go = *(const float*)cl.map_shared_rank((void*)&s[OFF_GTE + sl], 6 + r0);
            float cn = sigm(gf) * s[OFF_C + hh] + sigm(gi) * tanh_ex(gg);
            float hn = sigm(go) * tanh_ex(cn);
            s[OFF_C + hh] = cn;
            s[OFF_H + hh] = hn;
            if (rank == 0) out[(size_t)(b * 128 + t) * 128 + hh] = hn;
        }
        __syncthreads();
    }

    cl.sync();   // no CTA exits while peers may still read its SMEM
}

extern "C" void kernel_launch(void* const* d_in, const int* in_sizes, int n_in,
                              void* d_out, int out_size) {
    (void)in_sizes; (void)n_in; (void)out_size;
    cudaFuncSetAttribute(mlstm_kernel, cudaFuncAttributeMaxDynamicSharedMemorySize,
                         SMEM_FLOATS * (int)sizeof(float));
    mlstm_kernel<<<128, TPB, SMEM_FLOATS * sizeof(float)>>>(
        (const float*)d_in[0],  (const float*)d_in[1],
        (const float*)d_in[2],  (const float*)d_in[3],
        (const float*)d_in[4],  (const float*)d_in[5],
        (const float*)d_in[6],  (const float*)d_in[7],
        (const float*)d_in[8],
        (const float*)d_in[10], (const float*)d_in[11],
        (const float*)d_in[12], (const float*)d_in[13],
        (const float*)d_in[14], (const float*)d_in[15],
        (float*)d_out);
}

// round 3
// speedup vs baseline: 1.2317x; 1.2317x over previous
#include <cuda_runtime.h>
#include <cooperative_groups.h>
#include <math_constants.h>

namespace cg = cooperative_groups;

#define CS   8
#define TPB  256

// ---- shared memory layout (float offsets) ----
static constexpr int OFF_WRT  = 0;                 // 128*132 : WrT[d][h] pad132 (also Ws/Wt staging)
static constexpr int OFF_WHS  = 16896;             // 32*129  : Whs[q][h] pad129
static constexpr int OFF_WGT  = 21024;             // 256*33  : WgT[k][j] pad33 (also q/p staging)
static constexpr int OFF_WT   = 29472;             // 384*65  : [Wih;Whh]T[k][j] pad65
static constexpr int OFF_WE   = 54432;             // 128
static constexpr int OFF_WRB  = 54560;             // 128
static constexpr int OFF_WGB  = 54688;             // 32
static constexpr int OFF_BIHH = 54720;             // 64
static constexpr int OFF_U    = 54784;             // 128
static constexpr int OFF_H    = 54912;             // 128
static constexpr int OFF_C    = 55040;             // 16 (this CTA's h-slice cell state)
static constexpr int OFF_X    = 55056;             // 256 : [alpha, p_t]
static constexpr int OFF_XP   = 55312;             // 256 : gathered gated x
static constexpr int OFF_PART = 55568;             // 1024: cross-warp partial sums
static constexpr int OFF_PQ   = 56592;             // 32
static constexpr int OFF_COEF = 56624;             // 8
static constexpr int OFF_STAT = 56632;             // 4 : [0]=1/L [1]=m_loc [2]=l_loc
static constexpr int OFF_ACCE = 56636;             // 128 (exported)
static constexpr int OFF_XGE  = 56764;             // 32  (exported)
static constexpr int OFF_GT   = 56796;             // 64
static constexpr int OFF_HE   = 56860;             // 16  (exported)
static constexpr int SMEM_FLOATS = 56876;          // 227504 bytes

__device__ float g_wtp[16 * 128 * 128];   // wt_pre scratch [B][P][H]

__device__ __forceinline__ float fast_tanh(float x) {
    float y; asm("tanh.approx.f32 %0, %1;" : "=f"(y) : "f"(x)); return y;
}
__device__ __forceinline__ float sigm(float x) {
    return __fdividef(1.f, 1.f + __expf(-x));
}
__device__ __forceinline__ float tanh_ex(float x) {
    float e = __expf(2.f * x);
    return 1.f - __fdividef(2.f, e + 1.f);
}
__device__ __forceinline__ float warp_sum(float v) {
    #pragma unroll
    for (int o = 16; o; o >>= 1) v += __shfl_xor_sync(0xffffffffu, v, o);
    return v;
}
__device__ __forceinline__ float warp_max(float v) {
    #pragma unroll
    for (int o = 16; o; o >>= 1) v = fmaxf(v, __shfl_xor_sync(0xffffffffu, v, o));
    return v;
}

__global__ void __launch_bounds__(TPB, 1) __cluster_dims__(CS, 1, 1)
mlstm_kernel(const float* __restrict__ p_in,  const float* __restrict__ q_in,
             const float* __restrict__ Ws_w,  const float* __restrict__ Ws_b,
             const float* __restrict__ Wt_w,  const float* __restrict__ Wt_b,
             const float* __restrict__ Wr_w,  const float* __restrict__ Wr_b,
             const float* __restrict__ We_w,
             const float* __restrict__ Wg_w,  const float* __restrict__ Wg_b,
             const float* __restrict__ Wih,   const float* __restrict__ Whh,
             const float* __restrict__ bih,   const float* __restrict__ bhh,
             float* __restrict__ out)
{
    extern __shared__ float s[];
    cg::cluster_group cl = cg::this_cluster();
    const int rank = (int)cl.block_rank();
    const int b    = (int)(blockIdx.x >> 3);
    const int tid  = (int)threadIdx.x;
    const int lane = tid & 31;
    const int warp = tid >> 5;

    // ============================ PROLOGUE ============================
    // P1: Whs = q(32 rows) @ Ws^T + b   (stage Ws pad132 in WRT, q in WGT region)
    for (int i4 = tid; i4 < 4096; i4 += TPB) {
        int hh = i4 >> 5, k = i4 & 31;
        *(float4*)&s[OFF_WRT + hh * 132 + k * 4] = ((const float4*)Ws_w)[i4];
    }
    for (int i4 = tid; i4 < 1024; i4 += TPB)
        ((float4*)&s[OFF_WGT])[i4] = ((const float4*)(q_in + (size_t)(b * 256 + rank * 32) * 128))[i4];
    __syncthreads();
    {
        int hh = tid & 127, q0 = (tid >> 7) * 16;
        const float4* wrow = (const float4*)&s[OFF_WRT + hh * 132];
        float acc[16];
        float sb = Ws_b[hh];
        #pragma unroll
        for (int i = 0; i < 16; i++) acc[i] = sb;
        for (int k = 0; k < 32; k++) {
            float4 w = wrow[k];
            #pragma unroll
            for (int i = 0; i < 16; i++) {
                float4 qv = *(const float4*)&s[OFF_WGT + (q0 + i) * 128 + k * 4];
                acc[i] += w.x * qv.x + w.y * qv.y + w.z * qv.z + w.w * qv.w;
            }
        }
        #pragma unroll
        for (int i = 0; i < 16; i++) s[OFF_WHS + (q0 + i) * 129 + hh] = acc[i];
    }
    __syncthreads();

    // P2: wt_pre = p(16 rows) @ Wt^T + b  -> gmem
    for (int i4 = tid; i4 < 4096; i4 += TPB) {
        int hh = i4 >> 5, k = i4 & 31;
        *(float4*)&s[OFF_WRT + hh * 132 + k * 4] = ((const float4*)Wt_w)[i4];
    }
    for (int i4 = tid; i4 < 512; i4 += TPB)
        ((float4*)&s[OFF_WGT])[i4] = ((const float4*)(p_in + (size_t)(b * 128 + rank * 16) * 128))[i4];
    __syncthreads();
    {
        int hh = tid & 127, t0 = (tid >> 7) * 8;
        const float4* wrow = (const float4*)&s[OFF_WRT + hh * 132];
        float acc[8];
        float bt = Wt_b[hh];
        #pragma unroll
        for (int i = 0; i < 8; i++) acc[i] = bt;
        for (int k = 0; k < 32; k++) {
            float4 w = wrow[k];
            #pragma unroll
            for (int i = 0; i < 8; i++) {
                float4 pv = *(const float4*)&s[OFF_WGT + (t0 + i) * 128 + k * 4];
                acc[i] += w.x * pv.x + w.y * pv.y + w.z * pv.z + w.w * pv.w;
            }
        }
        #pragma unroll
        for (int i = 0; i < 8; i++)
            g_wtp[(size_t)(b * 128 + rank * 16 + t0 + i) * 128 + hh] = acc[i];
    }
    __syncthreads();

    // P3: WrT[d][h] (pad132) — coalesced gmem read, transposed smem write
    for (int idx = tid; idx < 16384; idx += TPB) {
        int hh = idx >> 7, dd = idx & 127;
        s[OFF_WRT + dd * 132 + hh] = Wr_w[idx];
    }
    // P4: WT[k][j] pad65 : j<16 -> i-gate row rank*16+j, 16..31 -> f, 32..47 -> g, 48..63 -> o
    for (int idx = tid; idx < 16384; idx += TPB) {
        int j = idx >> 8, k = idx & 255;
        int grow = (j >> 4) * 128 + rank * 16 + (j & 15);
        s[OFF_WT + k * 65 + j] = Wih[(size_t)grow * 256 + k];
    }
    for (int idx = tid; idx < 8192; idx += TPB) {
        int j = idx >> 7, k = idx & 127;
        int grow = (j >> 4) * 128 + rank * 16 + (j & 15);
        s[OFF_WT + (256 + k) * 65 + j] = Whh[(size_t)grow * 128 + k];
    }
    // P5: WgT[k][j] pad33 (rows rank*32+j)
    for (int idx = tid; idx < 8192; idx += TPB) {
        int j = idx >> 8, k = idx & 255;
        s[OFF_WGT + k * 33 + j] = Wg_w[(size_t)(rank * 32 + j) * 256 + k];
    }
    if (tid < 128) {
        s[OFF_WE  + tid] = We_w[tid];
        s[OFF_WRB + tid] = Wr_b[tid];
        s[OFF_H   + tid] = 0.f;
    }
    if (tid < 16) s[OFF_C + tid] = 0.f;
    if (tid < 32) s[OFF_WGB + tid] = Wg_b[rank * 32 + tid];
    if (tid < 64) {
        int grow = (tid >> 4) * 128 + rank * 16 + (tid & 15);
        s[OFF_BIHH + tid] = bih[grow] + bhh[grow];
    }
    __threadfence();   // g_wtp visible cluster-wide
    __syncthreads();
    cl.sync();

    // ============================ MAIN LOOP ============================
    for (int t = 0; t < 128; t++) {
        // ---- A: u = wt_pre[t] + Wr_b + Wr @ h (lane=4h, warp=d-chunk 16) ----
        float wtpv = (tid < 128) ? g_wtp[(size_t)(b * 128 + t) * 128 + tid] : 0.f;
        float ptv  = (tid < 128) ? p_in[(size_t)(b * 128 + t) * 128 + tid] : 0.f;
        {
            float4 a4 = {0.f, 0.f, 0.f, 0.f};
            #pragma unroll
            for (int dd = 0; dd < 16; dd++) {
                int d = warp * 16 + dd;
                float hb = s[OFF_H + d];
                float4 w4 = *(const float4*)&s[OFF_WRT + d * 132 + 4 * lane];
                a4.x += w4.x * hb; a4.y += w4.y * hb; a4.z += w4.z * hb; a4.w += w4.w * hb;
            }
            *(float4*)&s[OFF_PART + warp * 128 + 4 * lane] = a4;
        }
        if (tid < 128) s[OFF_X + 128 + tid] = ptv;
        __syncthreads();
        if (tid < 128) {
            float u = wtpv + s[OFF_WRB + tid];
            #pragma unroll
            for (int w = 0; w < 8; w++) u += s[OFF_PART + w * 128 + tid];
            s[OFF_U + tid] = u;
        }
        __syncthreads();

        // ---- B: scores (lane=q, warp=h-chunk 16); softmax partials; acc ----
        {
            float sc = 0.f;
            #pragma unroll
            for (int dd = 0; dd < 16; dd++) {
                int h = warp * 16 + dd;
                sc += fast_tanh(s[OFF_WHS + lane * 129 + h] + s[OFF_U + h]) * s[OFF_WE + h];
            }
            s[OFF_PART + warp * 32 + lane] = sc;
        }
        __syncthreads();
        if (tid < 32) {
            float sc = 0.f;
            #pragma unroll
            for (int w = 0; w < 8; w++) sc += s[OFF_PART + w * 32 + tid];
            float m = warp_max(sc);
            float e = __expf(sc - m);
            s[OFF_PQ + tid] = e;
            float l = warp_sum(e);
            if (tid == 0) { s[OFF_STAT + 1] = m; s[OFF_STAT + 2] = l; }
        }
        __syncthreads();
        if (tid < 128) {
            float a = 0.f;
            #pragma unroll
            for (int q = 0; q < 32; q++)
                a += s[OFF_PQ + q] * s[OFF_WHS + q * 129 + tid];
            s[OFF_ACCE + tid] = a;
        }
        cl.sync();   // barrier 1

        // ---- C: softmax combine across cluster; alpha -> x[0:128] ----
        if (tid < 32) {
            float mi = -CUDART_INF_F, li = 0.f;
            if (lane < 8) {
                const float* st = (const float*)cl.map_shared_rank((void*)&s[OFF_STAT], lane);
                mi = st[1]; li = st[2];
            }
            float M  = warp_max(mi);
            float cf = (lane < 8) ? __expf(mi - M) : 0.f;
            if (lane < 8) s[OFF_COEF + lane] = cf;
            float L = warp_sum(cf * li);
            if (lane == 0) s[OFF_STAT] = 1.f / L;
        }
        __syncthreads();
        if (tid < 128) {
            float a = 0.f;
            #pragma unroll
            for (int r = 0; r < 8; r++) {
                const float* ap = (const float*)cl.map_shared_rank((void*)&s[OFF_ACCE + tid], r);
                a += s[OFF_COEF + r] * ap[0];
            }
            s[OFF_X + tid] = a * s[OFF_STAT];
        }
        __syncthreads();

        // ---- D: gate slice (lane=j, warp=k-chunk 32); export x' = g*x slice ----
        {
            float pp = 0.f;
            #pragma unroll 8
            for (int kk = 0; kk < 32; kk++) {
                int k = warp * 32 + kk;
                pp += s[OFF_WGT + k * 33 + lane] * s[OFF_X + k];
            }
            s[OFF_PART + warp * 32 + lane] = pp;
        }
        __syncthreads();
        if (tid < 32) {
            float sum = 0.f;
            #pragma unroll
            for (int w = 0; w < 8; w++) sum += s[OFF_PART + w * 32 + tid];
            float g = sigm(sum + s[OFF_WGB + tid]);
            s[OFF_XGE + tid] = g * s[OFF_X + rank * 32 + tid];
        }
        cl.sync();   // barrier 2

        // ---- E: gather x'; LSTM gate pre-acts (lane=j(+32), warp=k-chunk 48) ----
        s[OFF_XP + tid] = *(const float*)cl.map_shared_rank((void*)&s[OFF_XGE + (tid & 31)], tid >> 5);
        __syncthreads();
        {
            float a0 = 0.f, a1 = 0.f;
            #pragma unroll 8
            for (int kk = 0; kk < 48; kk++) {
                int k = warp * 48 + kk;
                float xv = s[(k < 256) ? (OFF_XP + k) : (OFF_H + k - 256)];
                a0 += s[OFF_WT + k * 65 + lane] * xv;
                a1 += s[OFF_WT + k * 65 + 32 + lane] * xv;
            }
            s[OFF_PART + warp * 64 + lane]      = a0;
            s[OFF_PART + warp * 64 + 32 + lane] = a1;
        }
        __syncthreads();
        if (tid < 64) {
            float g = s[OFF_BIHH + tid];
            #pragma unroll
            for (int w = 0; w < 8; w++) g += s[OFF_PART + w * 64 + tid];
            s[OFF_GT + tid] = g;
        }
        __syncthreads();
        if (tid < 16) {
            float gi = s[OFF_GT + tid],      gf = s[OFF_GT + 16 + tid];
            float gg = s[OFF_GT + 32 + tid], go = s[OFF_GT + 48 + tid];
            float cn = sigm(gf) * s[OFF_C + tid] + sigm(gi) * tanh_ex(gg);
            float hn = sigm(go) * tanh_ex(cn);
            s[OFF_C + tid]  = cn;
            s[OFF_HE + tid] = hn;
            out[(size_t)(b * 128 + t) * 128 + rank * 16 + tid] = hn;
        }
        cl.sync();   // barrier 3

        // ---- F: gather new h ----
        if (tid < 128)
            s[OFF_H + tid] = *(const float*)cl.map_shared_rank((void*)&s[OFF_HE + (tid & 15)], tid >> 4);
        __syncthreads();
    }

    cl.sync();
}

extern "C" void kernel_launch(void* const* d_in, const int* in_sizes, int n_in,
                              void* d_out, int out_size) {
    (void)in_sizes; (void)n_in; (void)out_size;
    cudaFuncSetAttribute(mlstm_kernel, cudaFuncAttributeMaxDynamicSharedMemorySize,
                         SMEM_FLOATS * (int)sizeof(float));
    mlstm_kernel<<<128, TPB, SMEM_FLOATS * sizeof(float)>>>(
        (const float*)d_in[0],  (const float*)d_in[1],
        (const float*)d_in[2],  (const float*)d_in[3],
        (const float*)d_in[4],  (const float*)d_in[5],
        (const float*)d_in[6],  (const float*)d_in[7],
        (const float*)d_in[8],
        (const float*)d_in[10], (const float*)d_in[11],
        (const float*)d_in[12], (const float*)d_in[13],
        (const float*)d_in[14], (const float*)d_in[15],
        (float*)d_out);
}

// round 5
// speedup vs baseline: 1.3010x; 1.0563x over previous
#include <cuda_runtime.h>
#include <cooperative_groups.h>
#include <math_constants.h>

namespace cg = cooperative_groups;

#define CS   8
#define TPB  256

// ---- shared memory layout (float offsets) ----
static constexpr int OFF_WRT  = 0;                 // 128*129 : WrT[d][h] pad129
static constexpr int OFF_WHS  = 16512;             // 32*129  : Whs[q][h] pad129
static constexpr int OFF_WGT  = 20640;             // 256*33  : WgT[k][j] pad33 (staging q/p)
static constexpr int OFF_WT   = 29088;             // 384*66  : [Wih;Whh]T[k][j] pad66 (staging Ws/Wt pad132)
static constexpr int OFF_WE   = 54432;             // 128
static constexpr int OFF_WRB  = 54560;             // 128
static constexpr int OFF_WGB  = 54688;             // 32
static constexpr int OFF_BIHH = 54720;             // 64
static constexpr int OFF_U    = 54784;             // 128
static constexpr int OFF_HB   = 54912;             // 2*128 : double-buffered h
static constexpr int OFF_C    = 55168;             // 16
static constexpr int OFF_X    = 55184;             // 256 : [alpha, p_t]
static constexpr int OFF_XP   = 55440;             // 256 : gated x (pushed by peers)
static constexpr int OFF_PART = 55696;             // 512
static constexpr int OFF_PQ   = 56208;             // 32
static constexpr int OFF_ACB  = 56240;             // 8*128 : acc buffers (pushed)
static constexpr int OFF_LB   = 57264;             // 8     : l buffers (pushed)
static constexpr int SMEM_FLOATS = 57272;          // 229088 bytes

__device__ float g_wtp[16 * 128 * 128];   // wt_pre scratch [B][P][H]

__device__ __forceinline__ float fast_tanh(float x) {
    float y; asm("tanh.approx.f32 %0, %1;" : "=f"(y) : "f"(x)); return y;
}
__device__ __forceinline__ float sigm(float x) {
    return __fdividef(1.f, 1.f + __expf(-x));
}
__device__ __forceinline__ float tanh_ex(float x) {
    float e = __expf(2.f * x);
    return 1.f - __fdividef(2.f, e + 1.f);
}
__device__ __forceinline__ float warp_sum(float v) {
    #pragma unroll
    for (int o = 16; o; o >>= 1) v += __shfl_xor_sync(0xffffffffu, v, o);
    return v;
}
// posted remote shared store (push)
__device__ __forceinline__ void dsmem_st(const float* localp, int r, float v) {
    uint32_t l = (uint32_t)__cvta_generic_to_shared(localp), rm;
    asm("mapa.shared::cluster.u32 %0, %1, %2;" : "=r"(rm) : "r"(l), "r"(r));
    asm volatile("st.shared::cluster.f32 [%0], %1;" :: "r"(rm), "f"(v) : "memory");
}
__device__ __forceinline__ void csync() {
    asm volatile("barrier.cluster.arrive.aligned;" ::: "memory");
    asm volatile("barrier.cluster.wait.aligned;" ::: "memory");
}

__global__ void __launch_bounds__(TPB, 1) __cluster_dims__(CS, 1, 1)
mlstm_kernel(const float* __restrict__ p_in,  const float* __restrict__ q_in,
             const float* __restrict__ Ws_w,  const float* __restrict__ Ws_b,
             const float* __restrict__ Wt_w,  const float* __restrict__ Wt_b,
             const float* __restrict__ Wr_w,  const float* __restrict__ Wr_b,
             const float* __restrict__ We_w,
             const float* __restrict__ Wg_w,  const float* __restrict__ Wg_b,
             const float* __restrict__ Wih,   const float* __restrict__ Whh,
             const float* __restrict__ bih,   const float* __restrict__ bhh,
             float* __restrict__ out)
{
    extern __shared__ float s[];
    cg::cluster_group cl = cg::this_cluster();
    const int rank = (int)cl.block_rank();
    const int b    = (int)(blockIdx.x >> 3);
    const int tid  = (int)threadIdx.x;
    const int lane = tid & 31;
    const int warp = tid >> 5;

    // ============================ PROLOGUE ============================
    // P1: Whs = q(32 rows) @ Ws^T + b  (Ws staged pad132 at OFF_WT, q at OFF_WGT)
    for (int i4 = tid; i4 < 4096; i4 += TPB) {
        int hh = i4 >> 5, k = i4 & 31;
        *(float4*)&s[OFF_WT + hh * 132 + k * 4] = ((const float4*)Ws_w)[i4];
    }
    for (int i4 = tid; i4 < 1024; i4 += TPB)
        ((float4*)&s[OFF_WGT])[i4] = ((const float4*)(q_in + (size_t)(b * 256 + rank * 32) * 128))[i4];
    __syncthreads();
    {
        int hh = tid & 127, q0 = (tid >> 7) * 16;
        const float4* wrow = (const float4*)&s[OFF_WT + hh * 132];
        float acc[16];
        float sb = Ws_b[hh];
        #pragma unroll
        for (int i = 0; i < 16; i++) acc[i] = sb;
        for (int k = 0; k < 32; k++) {
            float4 w = wrow[k];
            #pragma unroll
            for (int i = 0; i < 16; i++) {
                float4 qv = *(const float4*)&s[OFF_WGT + (q0 + i) * 128 + k * 4];
                acc[i] += w.x * qv.x + w.y * qv.y + w.z * qv.z + w.w * qv.w;
            }
        }
        #pragma unroll
        for (int i = 0; i < 16; i++) s[OFF_WHS + (q0 + i) * 129 + hh] = acc[i];
    }
    __syncthreads();

    // P2: wt_pre = p(16 rows) @ Wt^T + b -> gmem scratch
    for (int i4 = tid; i4 < 4096; i4 += TPB) {
        int hh = i4 >> 5, k = i4 & 31;
        *(float4*)&s[OFF_WT + hh * 132 + k * 4] = ((const float4*)Wt_w)[i4];
    }
    for (int i4 = tid; i4 < 512; i4 += TPB)
        ((float4*)&s[OFF_WGT])[i4] = ((const float4*)(p_in + (size_t)(b * 128 + rank * 16) * 128))[i4];
    __syncthreads();
    {
        int hh = tid & 127, t0 = (tid >> 7) * 8;
        const float4* wrow = (const float4*)&s[OFF_WT + hh * 132];
        float acc[8];
        float bt = Wt_b[hh];
        #pragma unroll
        for (int i = 0; i < 8; i++) acc[i] = bt;
        for (int k = 0; k < 32; k++) {
            float4 w = wrow[k];
            #pragma unroll
            for (int i = 0; i < 8; i++) {
                float4 pv = *(const float4*)&s[OFF_WGT + (t0 + i) * 128 + k * 4];
                acc[i] += w.x * pv.x + w.y * pv.y + w.z * pv.z + w.w * pv.w;
            }
        }
        #pragma unroll
        for (int i = 0; i < 8; i++)
            g_wtp[(size_t)(b * 128 + rank * 16 + t0 + i) * 128 + hh] = acc[i];
    }
    __syncthreads();

    // P3: WrT[d][h] pad129
    for (int idx = tid; idx < 16384; idx += TPB) {
        int hh = idx >> 7, dd = idx & 127;
        s[OFF_WRT + dd * 129 + hh] = Wr_w[idx];
    }
    // P4: WT[k][j] pad66 ; j>>4 = gate (i,f,g,o), j&15 = h-slot in my 16
    for (int idx = tid; idx < 16384; idx += TPB) {
        int j = idx >> 8, k = idx & 255;
        int grow = (j >> 4) * 128 + rank * 16 + (j & 15);
        s[OFF_WT + k * 66 + j] = Wih[(size_t)grow * 256 + k];
    }
    for (int idx = tid; idx < 8192; idx += TPB) {
        int j = idx >> 7, k = idx & 127;
        int grow = (j >> 4) * 128 + rank * 16 + (j & 15);
        s[OFF_WT + (256 + k) * 66 + j] = Whh[(size_t)grow * 128 + k];
    }
    // P5: WgT[k][j] pad33
    for (int idx = tid; idx < 8192; idx += TPB) {
        int j = idx >> 8, k = idx & 255;
        s[OFF_WGT + k * 33 + j] = Wg_w[(size_t)(rank * 32 + j) * 256 + k];
    }
    if (tid < 128) {
        s[OFF_WE  + tid] = We_w[tid];
        s[OFF_WRB + tid] = Wr_b[tid];
        s[OFF_HB  + tid] = 0.f;           // h buffer 0
        s[OFF_HB + 128 + tid] = 0.f;      // h buffer 1
    }
    if (tid < 16) s[OFF_C + tid] = 0.f;
    if (tid < 32) s[OFF_WGB + tid] = Wg_b[rank * 32 + tid];
    if (tid < 64) {
        int grow = (tid >> 4) * 128 + rank * 16 + (tid & 15);
        s[OFF_BIHH + tid] = bih[grow] + bhh[grow];
    }
    __threadfence();     // g_wtp visible cluster-wide
    __syncthreads();
    csync();

    // ============================ MAIN LOOP ============================
    for (int t = 0; t < 128; t++) {
        const int hcur = OFF_HB + (t & 1) * 128;
        const int hnxt = OFF_HB + ((t + 1) & 1) * 128;

        // ---- A: warps 0-3: u[32 each] = wtp + b + Wr@h ; warps 4-7: p_t ----
        if (warp < 4) {
            int hh = warp * 32 + lane;
            float wtpv = g_wtp[(size_t)(b * 128 + t) * 128 + hh];   // issue early
            float a0 = 0.f, a1 = 0.f, a2 = 0.f, a3 = 0.f;
            #pragma unroll 8
            for (int d = 0; d < 128; d += 4) {
                float4 h4 = *(const float4*)&s[hcur + d];
                a0 += s[OFF_WRT + (d + 0) * 129 + hh] * h4.x;
                a1 += s[OFF_WRT + (d + 1) * 129 + hh] * h4.y;
                a2 += s[OFF_WRT + (d + 2) * 129 + hh] * h4.z;
                a3 += s[OFF_WRT + (d + 3) * 129 + hh] * h4.w;
            }
            s[OFF_U + hh] = wtpv + s[OFF_WRB + hh] + ((a0 + a1) + (a2 + a3));
        } else {
            int j = (warp - 4) * 32 + lane;
            s[OFF_X + 128 + j] = p_in[(size_t)(b * 128 + t) * 128 + j];
        }
        __syncthreads();   // S1

        // ---- B: each warp computes 4 q scores via in-warp reduction ----
        {
            int q0 = warp * 4;
            float s0 = 0.f, s1 = 0.f, s2 = 0.f, s3 = 0.f;
            #pragma unroll
            for (int c = 0; c < 4; c++) {
                int h = c * 32 + lane;
                float uh = s[OFF_U + h];
                float we = s[OFF_WE + h];
                s0 += fast_tanh(s[OFF_WHS + (q0 + 0) * 129 + h] + uh) * we;
                s1 += fast_tanh(s[OFF_WHS + (q0 + 1) * 129 + h] + uh) * we;
                s2 += fast_tanh(s[OFF_WHS + (q0 + 2) * 129 + h] + uh) * we;
                s3 += fast_tanh(s[OFF_WHS + (q0 + 3) * 129 + h] + uh) * we;
            }
            s0 = warp_sum(s0); s1 = warp_sum(s1); s2 = warp_sum(s2); s3 = warp_sum(s3);
            if (lane == 0) {   // no-max softmax: scores bounded by ||We||_1 ~ 5
                s[OFF_PQ + q0 + 0] = __expf(s0);
                s[OFF_PQ + q0 + 1] = __expf(s1);
                s[OFF_PQ + q0 + 2] = __expf(s2);
                s[OFF_PQ + q0 + 3] = __expf(s3);
            }
        }
        __syncthreads();   // S2

        // ---- acc + l, PUSH to all peers ----
        if (tid < 128) {
            float a = 0.f;
            #pragma unroll
            for (int q = 0; q < 32; q++)
                a += s[OFF_PQ + q] * s[OFF_WHS + q * 129 + tid];
            const float* dst = &s[OFF_ACB + rank * 128 + tid];
            #pragma unroll
            for (int r = 0; r < CS; r++) dsmem_st(dst, r, a);
        } else if (warp == 4) {
            float l = warp_sum(s[OFF_PQ + lane]);
            if (lane == 0) {
                #pragma unroll
                for (int r = 0; r < CS; r++) dsmem_st(&s[OFF_LB + rank], r, l);
            }
        }
        csync();           // C1

        // ---- C: alpha = (sum_r acc_r) / (sum_r l_r) ----
        if (tid < 128) {
            float a = 0.f, L = 0.f;
            #pragma unroll
            for (int r = 0; r < CS; r++) {
                a += s[OFF_ACB + r * 128 + tid];
                L += s[OFF_LB + r];
            }
            s[OFF_X + tid] = __fdividef(a, L);
        }
        __syncthreads();   // S3

        // ---- D: gate partials (lane=j, warp=k-chunk 32) ----
        {
            float pp = 0.f;
            #pragma unroll 8
            for (int kk = 0; kk < 32; kk++) {
                int k = warp * 32 + kk;
                pp += s[OFF_WGT + k * 33 + lane] * s[OFF_X + k];
            }
            s[OFF_PART + warp * 32 + lane] = pp;
        }
        __syncthreads();   // S4
        if (tid < 32) {
            float sum = 0.f;
            #pragma unroll
            for (int w = 0; w < 8; w++) sum += s[OFF_PART + w * 32 + tid];
            float g  = sigm(sum + s[OFF_WGB + tid]);
            float xg = g * s[OFF_X + rank * 32 + tid];
            const float* dst = &s[OFF_XP + rank * 32 + tid];
            #pragma unroll
            for (int r = 0; r < CS; r++) dsmem_st(dst, r, xg);
        }
        csync();           // C2

        // ---- E: LSTM gate partials (lane covers j=2l,2l+1; warp=k-chunk 48) ----
        {
            float a0 = 0.f, a1 = 0.f;
            #pragma unroll 6
            for (int kk = 0; kk < 48; kk++) {
                int k = warp * 48 + kk;
                float xv = (k < 256) ? s[OFF_XP + k] : s[hcur + k - 256];
                float2 w2 = *(const float2*)&s[OFF_WT + k * 66 + 2 * lane];
                a0 += w2.x * xv; a1 += w2.y * xv;
            }
            float2 o2 = {a0, a1};
            *(float2*)&s[OFF_PART + warp * 64 + 2 * lane] = o2;
        }
        __syncthreads();   // S5
        if (tid < 16) {
            float g[4];
            #pragma unroll
            for (int gt = 0; gt < 4; gt++) {
                int j = gt * 16 + tid;
                float v = s[OFF_BIHH + j];
                #pragma unroll
                for (int w = 0; w < 8; w++) v += s[OFF_PART + w * 64 + j];
                g[gt] = v;
            }
            float cn = sigm(g[1]) * s[OFF_C + tid] + sigm(g[0]) * tanh_ex(g[2]);
            float hn = sigm(g[3]) * tanh_ex(cn);
            s[OFF_C + tid] = cn;
            out[(size_t)(b * 128 + t) * 128 + rank * 16 + tid] = hn;
            const float* dst = &s[hnxt + rank * 16 + tid];
            #pragma unroll
            for (int r = 0; r < CS; r++) dsmem_st(dst, r, hn);
        }
        csync();           // C3: h ready for next step
    }

    csync();
}

extern "C" void kernel_launch(void* const* d_in, const int* in_sizes, int n_in,
                              void* d_out, int out_size) {
    (void)in_sizes; (void)n_in; (void)out_size;
    cudaFuncSetAttribute(mlstm_kernel, cudaFuncAttributeMaxDynamicSharedMemorySize,
                         SMEM_FLOATS * (int)sizeof(float));
    mlstm_kernel<<<128, TPB, SMEM_FLOATS * sizeof(float)>>>(
        (const float*)d_in[0],  (const float*)d_in[1],
        (const float*)d_in[2],  (const float*)d_in[3],
        (const float*)d_in[4],  (const float*)d_in[5],
        (const float*)d_in[6],  (const float*)d_in[7],
        (const float*)d_in[8],
        (const float*)d_in[10], (const float*)d_in[11],
        (const float*)d_in[12], (const float*)d_in[13],
        (const float*)d_in[14], (const float*)d_in[15],
        (float*)d_out);
}